// round 1
// baseline (speedup 1.0000x reference)
#include <cuda_runtime.h>
#include <math.h>

#define BATCH 64
#define HW 56
#define CDIM 128
#define NHEADS 4
#define HD 32
#define WS 7
#define NTOK 49
#define SHIFT_SZ 3
#define NWIN_TOT 4096
#define HID 512
#define NPIX (BATCH*HW*HW)      // 200704
#define KSTRIDE 133             // padded k-row stride (conflict-free: 133 mod 32 = 5)

// ---------------- device scratch (no allocations allowed) ----------------
__device__ float g_attn_out[(size_t)NPIX * CDIM];   // ~103 MB
__device__ float g_bias16[13 * 13 * NHEADS];
__device__ float g_scale[NHEADS];

// ---------------- K1: relative position bias MLP + logit scales ----------------
__device__ __forceinline__ float rpb_f(float v) {
    float sv = v * (2.0f / 9.0f);              // /(pretrain-1) * 8/(pretrain-1)
    float s = (sv > 0.f) ? 1.f : ((sv < 0.f) ? -1.f : 0.f);
    return s * log1pf(fabsf(sv)) * (1.0f / 2.0794415416798357f); // /log(8)
}

__global__ void k_prep(const float* __restrict__ logit_scale,
                       const float* __restrict__ rpe_w1,
                       const float* __restrict__ rpe_b1,
                       const float* __restrict__ rpe_w2) {
    int t = threadIdx.x;
    if (t < NHEADS) g_scale[t] = expf(fminf(logit_scale[t], logf(100.0f)));
    for (int r = t; r < 169; r += blockDim.x) {
        int dy = r / 13 - 6;
        int dx = r % 13 - 6;
        float t0 = rpb_f((float)dy);   // table[...,0] = f(row-diff)
        float t1 = rpb_f((float)dx);   // table[...,1] = f(col-diff)
        float acc0 = 0.f, acc1 = 0.f, acc2 = 0.f, acc3 = 0.f;
        for (int k = 0; k < HID; ++k) {
            float hsum = fmaf(t0, rpe_w1[k], fmaf(t1, rpe_w1[HID + k], rpe_b1[k]));
            if (hsum > 0.f) {
                const float* w2r = rpe_w2 + k * 4;
                acc0 = fmaf(hsum, w2r[0], acc0);
                acc1 = fmaf(hsum, w2r[1], acc1);
                acc2 = fmaf(hsum, w2r[2], acc2);
                acc3 = fmaf(hsum, w2r[3], acc3);
            }
        }
        g_bias16[r * 4 + 0] = 16.f / (1.f + expf(-acc0));
        g_bias16[r * 4 + 1] = 16.f / (1.f + expf(-acc1));
        g_bias16[r * 4 + 2] = 16.f / (1.f + expf(-acc2));
        g_bias16[r * 4 + 3] = 16.f / (1.f + expf(-acc3));
    }
}

// ---------------- K2: windowed attention (one block per window) ----------------
// smem: q[49*128] (reused as attn-out), k[49*133], v[49*128], at[4*49*49]
#define SMEM_ATTN_FLOATS (NTOK*CDIM + NTOK*KSTRIDE + NTOK*CDIM + NHEADS*NTOK*NTOK)

__global__ void __launch_bounds__(256, 2) k_attn(
    const float* __restrict__ x, const float* __restrict__ mask,
    const float* __restrict__ qkv_w, const float* __restrict__ q_bias,
    const float* __restrict__ v_bias, const float* __restrict__ proj_w,
    const float* __restrict__ proj_b) {
    extern __shared__ float sm[];
    float* q  = sm;                         // 49*128 ; reused for attn output
    float* kk = q + NTOK * CDIM;            // 49*133
    float* v  = kk + NTOK * KSTRIDE;        // 49*128
    float* at = v + NTOK * CDIM;            // 4*49*49
    __shared__ int pix[NTOK];

    int t = threadIdx.x;
    int win = blockIdx.x;
    int b = win >> 6, wloc = win & 63, wr = wloc >> 3, wc = wloc & 7;

    if (t < NTOK) {
        int i = t / WS, j = t % WS;
        int sr = (wr * WS + i + SHIFT_SZ) % HW;  // roll(-s) load == roll(+s) store
        int sc = (wc * WS + j + SHIFT_SZ) % HW;
        pix[t] = ((b * HW + sr) * HW + sc) * CDIM;
    }
    __syncthreads();

    // qkv = xw @ W + (q_bias, 0, v_bias)
    for (int idx = t; idx < NTOK * 384; idx += 256) {
        int p = idx / 384, c = idx % 384;
        const float* xr = x + pix[p];
        float acc = (c < 128) ? q_bias[c] : (c >= 256 ? v_bias[c - 256] : 0.f);
        #pragma unroll 8
        for (int k2 = 0; k2 < CDIM; ++k2) acc = fmaf(xr[k2], qkv_w[k2 * 384 + c], acc);
        if (c < 128)       q[p * CDIM + c] = acc;
        else if (c < 256)  kk[p * KSTRIDE + (c - 128)] = acc;
        else               v[p * CDIM + (c - 256)] = acc;
    }
    __syncthreads();

    // cosine-normalize q and k per (token, head)
    for (int idx = t; idx < 2 * NTOK * NHEADS; idx += 256) {
        int isk = idx / (NTOK * NHEADS);
        int rem = idx % (NTOK * NHEADS);
        int p = rem >> 2, h = rem & 3;
        float* base = isk ? (kk + p * KSTRIDE + h * HD) : (q + p * CDIM + h * HD);
        float s = 0.f;
        #pragma unroll
        for (int d = 0; d < HD; ++d) s = fmaf(base[d], base[d], s);
        float inv = rsqrtf(fmaxf(s, 1e-12f));
        #pragma unroll
        for (int d = 0; d < HD; ++d) base[d] *= inv;
    }
    __syncthreads();

    // scores = qn.kn * scale + 16*sigmoid(bias) + mask
    const float* mw = mask + (size_t)wloc * (NTOK * NTOK);
    for (int idx = t; idx < NHEADS * NTOK * NTOK; idx += 256) {
        int h = idx / (NTOK * NTOK);
        int rem = idx % (NTOK * NTOK);
        int p = rem / NTOK, qq = rem % NTOK;
        const float* qr = q + p * CDIM + h * HD;
        const float* kr = kk + qq * KSTRIDE + h * HD;
        float acc = 0.f;
        #pragma unroll
        for (int d = 0; d < HD; ++d) acc = fmaf(qr[d], kr[d], acc);
        int dy = p / WS - qq / WS + 6;
        int dx = p % WS - qq % WS + 6;
        at[idx] = fmaf(acc, g_scale[h], g_bias16[(dy * 13 + dx) * 4 + h] + mw[rem]);
    }
    __syncthreads();

    // softmax rows
    for (int idx = t; idx < NHEADS * NTOK; idx += 256) {
        float* row = at + idx * NTOK;
        float m = -1e30f;
        #pragma unroll 7
        for (int qq = 0; qq < NTOK; ++qq) m = fmaxf(m, row[qq]);
        float s = 0.f;
        #pragma unroll 7
        for (int qq = 0; qq < NTOK; ++qq) { float e = expf(row[qq] - m); row[qq] = e; s += e; }
        float inv = 1.f / s;
        #pragma unroll 7
        for (int qq = 0; qq < NTOK; ++qq) row[qq] *= inv;
    }
    __syncthreads();

    // o = attn @ v  (write into q; q fully consumed)
    for (int idx = t; idx < NTOK * CDIM; idx += 256) {
        int p = idx >> 7, c = idx & 127;
        int h = c >> 5;
        const float* ar = at + (h * NTOK + p) * NTOK;
        float acc = 0.f;
        #pragma unroll 7
        for (int qq = 0; qq < NTOK; ++qq) acc = fmaf(ar[qq], v[qq * CDIM + c], acc);
        q[idx] = acc;
    }
    __syncthreads();

    // proj and scatter back (un-shift == same pix index)
    for (int idx = t; idx < NTOK * CDIM; idx += 256) {
        int p = idx >> 7, c = idx & 127;
        const float* orow = q + p * CDIM;
        float acc = proj_b[c];
        #pragma unroll 8
        for (int j = 0; j < CDIM; ++j) acc = fmaf(orow[j], proj_w[j * CDIM + c], acc);
        g_attn_out[(size_t)pix[p] + c] = acc;
    }
}

// ---------------- K3: residual+LN, fused MLP, residual+LN ----------------
#define MLP_ROWS 32
#define SMEM_MLP_FLOATS (MLP_ROWS*CDIM + MLP_ROWS*HID + MLP_ROWS*CDIM)

__device__ __forceinline__ float gelu_exact(float z) {
    return 0.5f * z * (1.0f + erff(z * 0.7071067811865475f));
}

__global__ void __launch_bounds__(256, 2) k_mlp(
    const float* __restrict__ x,
    const float* __restrict__ n1g, const float* __restrict__ n1b,
    const float* __restrict__ w1, const float* __restrict__ b1,
    const float* __restrict__ w2, const float* __restrict__ b2,
    const float* __restrict__ n2g, const float* __restrict__ n2b,
    float* __restrict__ out) {
    extern __shared__ float sm[];
    float* x1 = sm;                         // 32*128
    float* hh = x1 + MLP_ROWS * CDIM;       // 32*512
    float* oo = hh + MLP_ROWS * HID;        // 32*128
    int t = threadIdx.x;
    int lane = t & 31, warp = t >> 5;
    size_t rowbase = (size_t)blockIdx.x * MLP_ROWS;

    // x1 = x + LN(attn_out)     (warp per row)
    for (int r = warp; r < MLP_ROWS; r += 8) {
        const float* y  = g_attn_out + (rowbase + r) * CDIM;
        const float* xr = x + (rowbase + r) * CDIM;
        float vb[4]; float s = 0.f;
        #pragma unroll
        for (int u = 0; u < 4; ++u) { vb[u] = y[lane + 32 * u]; s += vb[u]; }
        #pragma unroll
        for (int o = 16; o; o >>= 1) s += __shfl_xor_sync(0xffffffffu, s, o);
        float m = s * (1.f / 128.f);
        float vs = 0.f;
        #pragma unroll
        for (int u = 0; u < 4; ++u) { float d = vb[u] - m; vs = fmaf(d, d, vs); }
        #pragma unroll
        for (int o = 16; o; o >>= 1) vs += __shfl_xor_sync(0xffffffffu, vs, o);
        float inv = rsqrtf(vs * (1.f / 128.f) + 1e-3f);
        #pragma unroll
        for (int u = 0; u < 4; ++u) {
            int c = lane + 32 * u;
            x1[r * CDIM + c] = xr[c] + (vb[u] - m) * inv * n1g[c] + n1b[c];
        }
    }
    __syncthreads();

    int rg = t >> 6;      // 0..3 -> 8-row group
    int cg = t & 63;      // column group

    // GEMM1: hh = gelu(x1 @ w1 + b1), 8 rows x 8 cols per thread
    {
        float acc[8][8];
        #pragma unroll
        for (int a = 0; a < 8; ++a)
            #pragma unroll
            for (int u = 0; u < 8; ++u) acc[a][u] = 0.f;
        for (int k2 = 0; k2 < CDIM; ++k2) {
            float wv[8];
            #pragma unroll
            for (int u = 0; u < 8; ++u) wv[u] = w1[k2 * HID + cg + 64 * u];
            #pragma unroll
            for (int a = 0; a < 8; ++a) {
                float xv = x1[(rg * 8 + a) * CDIM + k2];
                #pragma unroll
                for (int u = 0; u < 8; ++u) acc[a][u] = fmaf(xv, wv[u], acc[a][u]);
            }
        }
        #pragma unroll
        for (int a = 0; a < 8; ++a)
            #pragma unroll
            for (int u = 0; u < 8; ++u) {
                int c = cg + 64 * u;
                hh[(rg * 8 + a) * HID + c] = gelu_exact(acc[a][u] + b1[c]);
            }
    }
    __syncthreads();

    // GEMM2: oo = hh @ w2 + b2, 8 rows x 2 cols per thread
    {
        float acc[8][2];
        #pragma unroll
        for (int a = 0; a < 8; ++a) { acc[a][0] = 0.f; acc[a][1] = 0.f; }
        for (int k2 = 0; k2 < HID; ++k2) {
            float w0 = w2[k2 * CDIM + cg];
            float w1v = w2[k2 * CDIM + cg + 64];
            #pragma unroll
            for (int a = 0; a < 8; ++a) {
                float hv = hh[(rg * 8 + a) * HID + k2];
                acc[a][0] = fmaf(hv, w0, acc[a][0]);
                acc[a][1] = fmaf(hv, w1v, acc[a][1]);
            }
        }
        #pragma unroll
        for (int a = 0; a < 8; ++a) {
            oo[(rg * 8 + a) * CDIM + cg]      = acc[a][0] + b2[cg];
            oo[(rg * 8 + a) * CDIM + cg + 64] = acc[a][1] + b2[cg + 64];
        }
    }
    __syncthreads();

    // out = x1 + LN(oo)
    for (int r = warp; r < MLP_ROWS; r += 8) {
        float vb[4]; float s = 0.f;
        #pragma unroll
        for (int u = 0; u < 4; ++u) { vb[u] = oo[r * CDIM + lane + 32 * u]; s += vb[u]; }
        #pragma unroll
        for (int o = 16; o; o >>= 1) s += __shfl_xor_sync(0xffffffffu, s, o);
        float m = s * (1.f / 128.f);
        float vs = 0.f;
        #pragma unroll
        for (int u = 0; u < 4; ++u) { float d = vb[u] - m; vs = fmaf(d, d, vs); }
        #pragma unroll
        for (int o = 16; o; o >>= 1) vs += __shfl_xor_sync(0xffffffffu, vs, o);
        float inv = rsqrtf(vs * (1.f / 128.f) + 1e-3f);
        #pragma unroll
        for (int u = 0; u < 4; ++u) {
            int c = lane + 32 * u;
            out[(rowbase + r) * CDIM + c] = x1[r * CDIM + c] + (vb[u] - m) * inv * n2g[c] + n2b[c];
        }
    }
}

// ---------------- launch ----------------
extern "C" void kernel_launch(void* const* d_in, const int* in_sizes, int n_in,
                              void* d_out, int out_size) {
    const float* x           = (const float*)d_in[0];
    const float* mask        = (const float*)d_in[1];
    const float* norm1_g     = (const float*)d_in[2];
    const float* norm1_b     = (const float*)d_in[3];
    const float* qkv_w       = (const float*)d_in[4];
    const float* q_bias      = (const float*)d_in[5];
    const float* v_bias      = (const float*)d_in[6];
    const float* logit_scale = (const float*)d_in[7];
    const float* rpe_w1      = (const float*)d_in[8];
    const float* rpe_b1      = (const float*)d_in[9];
    const float* rpe_w2      = (const float*)d_in[10];
    const float* proj_w      = (const float*)d_in[11];
    const float* proj_b      = (const float*)d_in[12];
    const float* norm2_g     = (const float*)d_in[13];
    const float* norm2_b     = (const float*)d_in[14];
    const float* fc1_w       = (const float*)d_in[15];
    const float* fc1_b       = (const float*)d_in[16];
    const float* fc2_w       = (const float*)d_in[17];
    const float* fc2_b       = (const float*)d_in[18];
    float* out = (float*)d_out;

    size_t smem_attn = SMEM_ATTN_FLOATS * sizeof(float);   // 114,660 B
    size_t smem_mlp  = SMEM_MLP_FLOATS * sizeof(float);    //  98,304 B
    cudaFuncSetAttribute(k_attn, cudaFuncAttributeMaxDynamicSharedMemorySize, (int)smem_attn);
    cudaFuncSetAttribute(k_mlp,  cudaFuncAttributeMaxDynamicSharedMemorySize, (int)smem_mlp);

    k_prep<<<1, 256>>>(logit_scale, rpe_w1, rpe_b1, rpe_w2);
    k_attn<<<NWIN_TOT, 256, smem_attn>>>(x, mask, qkv_w, q_bias, v_bias, proj_w, proj_b);
    k_mlp<<<NPIX / MLP_ROWS, 256, smem_mlp>>>(x, norm1_g, norm1_b,
                                              fc1_w, fc1_b, fc2_w, fc2_b,
                                              norm2_g, norm2_b, out);
}

// round 2
// speedup vs baseline: 2.6566x; 2.6566x over previous
#include <cuda_runtime.h>
#include <math.h>

#define HW 56
#define CDIM 128
#define WS 7
#define NTOK 49
#define NWIN_TOT 4096
#define NPIX 200704           // 64*56*56
#define QS 130                // q smem row stride (pairs: 65, odd -> conflict-free)
#define KS 134                // k smem row stride (pairs: 67, odd -> conflict-free)

typedef unsigned long long u64_t;

// ---------------- device scratch ----------------
__device__ float g_qkv[(size_t)NPIX * 384];      // 294 MB
__device__ float g_o[(size_t)NPIX * 128];        // 103 MB (attn@v out; reused for fc2 out)
__device__ float g_attn_out[(size_t)NPIX * 128]; // 103 MB
__device__ float g_x1[(size_t)NPIX * 128];       // 103 MB
__device__ float g_h[(size_t)NPIX * 512];        // 411 MB
__device__ float g_bias16[13 * 13 * 4];
__device__ float g_scale[4];
__device__ float g_qkvbias[384];

// ---------------- packed f32x2 FMA ----------------
__device__ __forceinline__ float2 ffma2(float2 a, float2 b, float2 c) {
    u64_t au = *reinterpret_cast<u64_t*>(&a);
    u64_t bu = *reinterpret_cast<u64_t*>(&b);
    u64_t cu = *reinterpret_cast<u64_t*>(&c);
    u64_t du;
    asm("fma.rn.f32x2 %0, %1, %2, %3;" : "=l"(du) : "l"(au), "l"(bu), "l"(cu));
    return *reinterpret_cast<float2*>(&du);
}

// ---------------- K1: prep (rpb table, scales, qkv bias) ----------------
__device__ __forceinline__ float rpb_f(float v) {
    float sv = v * (2.0f / 9.0f);
    float s = (sv > 0.f) ? 1.f : ((sv < 0.f) ? -1.f : 0.f);
    return s * log1pf(fabsf(sv)) * (1.0f / 2.0794415416798357f);
}

__global__ void k_prep(const float* __restrict__ logit_scale,
                       const float* __restrict__ rpe_w1,
                       const float* __restrict__ rpe_b1,
                       const float* __restrict__ rpe_w2,
                       const float* __restrict__ q_bias,
                       const float* __restrict__ v_bias) {
    int bid = blockIdx.x, t = threadIdx.x;
    if (bid == 169) {
        if (t < 4) g_scale[t] = expf(fminf(logit_scale[t], logf(100.0f)));
        for (int c = t; c < 384; c += 128)
            g_qkvbias[c] = (c < 128) ? q_bias[c] : (c >= 256 ? v_bias[c - 256] : 0.f);
        return;
    }
    int dy = bid / 13 - 6, dx = bid % 13 - 6;
    float t0 = rpb_f((float)dy), t1 = rpb_f((float)dx);
    float a0 = 0, a1 = 0, a2 = 0, a3 = 0;
    for (int k = t; k < 512; k += 128) {
        float hsum = fmaf(t0, rpe_w1[k], fmaf(t1, rpe_w1[512 + k], rpe_b1[k]));
        if (hsum > 0.f) {
            const float* w2r = rpe_w2 + k * 4;
            a0 = fmaf(hsum, w2r[0], a0);
            a1 = fmaf(hsum, w2r[1], a1);
            a2 = fmaf(hsum, w2r[2], a2);
            a3 = fmaf(hsum, w2r[3], a3);
        }
    }
    #pragma unroll
    for (int o = 16; o; o >>= 1) {
        a0 += __shfl_xor_sync(0xffffffffu, a0, o);
        a1 += __shfl_xor_sync(0xffffffffu, a1, o);
        a2 += __shfl_xor_sync(0xffffffffu, a2, o);
        a3 += __shfl_xor_sync(0xffffffffu, a3, o);
    }
    __shared__ float red[4][4];
    int w = t >> 5;
    if ((t & 31) == 0) { red[w][0] = a0; red[w][1] = a1; red[w][2] = a2; red[w][3] = a3; }
    __syncthreads();
    if (t < 4) {
        float s = red[0][t] + red[1][t] + red[2][t] + red[3][t];
        g_bias16[bid * 4 + t] = 16.f / (1.f + expf(-s));
    }
}

// ---------------- generic tiled GEMM: C[M x N] = A[M x K] @ B[K x N] ----------------
// BM=64, BN=128, BK=16, 256 threads, per-thread 8 rows x 4 cols (2 f32x2 pairs)
// EPI: 0=qkv bias -> g_qkv ; 1=proj bias + pixel scatter ; 2=gelu+bias ; 3=bias
__device__ __forceinline__ float gelu_exact(float z) {
    return 0.5f * z * (1.0f + erff(z * 0.7071067811865475f));
}

template<int K, int N, int EPI>
__global__ void __launch_bounds__(256) k_gemm(
    const float* __restrict__ A, const float* __restrict__ Bm,
    const float* __restrict__ bias, float* __restrict__ out)
{
    __shared__ __align__(16) float2 Asd[2][16][64];
    __shared__ __align__(16) float  Bs[2][16][128];
    int t = threadIdx.x;
    int tx = t & 31, ty = t >> 5;
    int bm = blockIdx.x * 64;
    int bn = blockIdx.y * 128;

    const int arow = t >> 2, akq = (t & 3) * 4;
    const int bk0 = t >> 5, bc0 = (t & 31) * 4;          // flat0 = t
    const int bk1 = (t + 256) >> 5, bc1 = bc0;           // flat1 = t+256

    float4 ra, rb0, rb1;
    // stage 0 loads
    ra  = *(const float4*)(A + (size_t)(bm + arow) * K + akq);
    rb0 = *(const float4*)(Bm + (size_t)bk0 * N + bn + bc0);
    rb1 = *(const float4*)(Bm + (size_t)bk1 * N + bn + bc1);
    // store stage 0
    Asd[0][akq + 0][arow] = make_float2(ra.x, ra.x);
    Asd[0][akq + 1][arow] = make_float2(ra.y, ra.y);
    Asd[0][akq + 2][arow] = make_float2(ra.z, ra.z);
    Asd[0][akq + 3][arow] = make_float2(ra.w, ra.w);
    *(float4*)&Bs[0][bk0][bc0] = rb0;
    *(float4*)&Bs[0][bk1][bc1] = rb1;
    __syncthreads();

    float2 acc[8][2];
    #pragma unroll
    for (int a = 0; a < 8; ++a) { acc[a][0] = make_float2(0.f, 0.f); acc[a][1] = make_float2(0.f, 0.f); }

    const int S = K / 16;
    #pragma unroll 1
    for (int s = 0; s < S; ++s) {
        if (s + 1 < S) {
            int kb = (s + 1) * 16;
            ra  = *(const float4*)(A + (size_t)(bm + arow) * K + kb + akq);
            rb0 = *(const float4*)(Bm + (size_t)(kb + bk0) * N + bn + bc0);
            rb1 = *(const float4*)(Bm + (size_t)(kb + bk1) * N + bn + bc1);
        }
        int buf = s & 1;
        #pragma unroll
        for (int kk = 0; kk < 16; ++kk) {
            const float2* b2 = (const float2*)Bs[buf][kk];
            float2 b0 = b2[tx];
            float2 b1 = b2[tx + 32];
            #pragma unroll
            for (int a = 0; a < 8; ++a) {
                float2 av = Asd[buf][kk][ty * 8 + a];
                acc[a][0] = ffma2(av, b0, acc[a][0]);
                acc[a][1] = ffma2(av, b1, acc[a][1]);
            }
        }
        __syncthreads();
        if (s + 1 < S) {
            int nb = (s + 1) & 1;
            Asd[nb][akq + 0][arow] = make_float2(ra.x, ra.x);
            Asd[nb][akq + 1][arow] = make_float2(ra.y, ra.y);
            Asd[nb][akq + 2][arow] = make_float2(ra.z, ra.z);
            Asd[nb][akq + 3][arow] = make_float2(ra.w, ra.w);
            *(float4*)&Bs[nb][bk0][bc0] = rb0;
            *(float4*)&Bs[nb][bk1][bc1] = rb1;
            __syncthreads();
        }
    }

    // epilogue
    int c0 = bn + 2 * tx, c1 = c0 + 64;
    #pragma unroll
    for (int a = 0; a < 8; ++a) {
        int r = bm + ty * 8 + a;
        float2 v0 = acc[a][0], v1 = acc[a][1];
        v0.x += bias[c0]; v0.y += bias[c0 + 1];
        v1.x += bias[c1]; v1.y += bias[c1 + 1];
        if (EPI == 2) {
            v0.x = gelu_exact(v0.x); v0.y = gelu_exact(v0.y);
            v1.x = gelu_exact(v1.x); v1.y = gelu_exact(v1.y);
        }
        if (EPI == 1) {
            unsigned r_ = (unsigned)r;
            unsigned win = r_ / 49u, p = r_ - win * 49u;
            unsigned b = win >> 6, wloc = win & 63u, wr = wloc >> 3, wc = wloc & 7u;
            unsigned i = p / 7u, j = p - i * 7u;
            unsigned sr = wr * 7 + i + 3; if (sr >= 56) sr -= 56;
            unsigned sc = wc * 7 + j + 3; if (sc >= 56) sc -= 56;
            size_t o = ((size_t)((b * 56 + sr) * 56 + sc)) * 128;
            *(float2*)(out + o + c0) = v0;
            *(float2*)(out + o + c1) = v1;
        } else {
            *(float2*)(out + (size_t)r * N + c0) = v0;
            *(float2*)(out + (size_t)r * N + c1) = v1;
        }
    }
}

// ---------------- K-core: per-window attention (scores/softmax/attn@v) ----------------
#define SMEM_CORE_FLOATS (NTOK*QS + NTOK*KS + NTOK*CDIM + 4*NTOK*NTOK)

__global__ void __launch_bounds__(256, 2) k_core(const float* __restrict__ mask) {
    extern __shared__ float sm[];
    float* q  = sm;                       // 49*130
    float* kk = q + NTOK * QS;            // 49*134
    float* v  = kk + NTOK * KS;           // 49*128
    float* at = v + NTOK * CDIM;          // 4*49*49
    __shared__ int pix[NTOK];

    int t = threadIdx.x;
    int win = blockIdx.x;
    int b = win >> 6, wloc = win & 63, wr = wloc >> 3, wc = wloc & 7;

    if (t < NTOK) {
        int i = t / WS, j = t % WS;
        int sr = (wr * WS + i + 3) % HW;
        int sc = (wc * WS + j + 3) % HW;
        pix[t] = (b * HW + sr) * HW + sc;
    }
    __syncthreads();

    // gather q/k/v rows (float2)
    for (int idx = t; idx < NTOK * 192; idx += 256) {
        int p = idx / 192, c2 = (idx % 192);
        float2 val = *(const float2*)(g_qkv + (size_t)pix[p] * 384 + c2 * 2);
        int c = c2 * 2;
        if (c < 128)       *(float2*)(q + p * QS + c) = val;
        else if (c < 256)  *(float2*)(kk + p * KS + (c - 128)) = val;
        else               *(float2*)(v + p * CDIM + (c - 256)) = val;
    }
    __syncthreads();

    // cosine-normalize q and k (per token, head); lanes map to consecutive p
    for (int idx = t; idx < 392; idx += 256) {
        int isk = idx / 196, rem = idx % 196, h = rem / 49, p = rem % 49;
        float2* base = isk ? (float2*)(kk + p * KS + h * 32) : (float2*)(q + p * QS + h * 32);
        float2 s2 = make_float2(0.f, 0.f);
        #pragma unroll
        for (int d = 0; d < 16; ++d) s2 = ffma2(base[d], base[d], s2);
        float inv = rsqrtf(fmaxf(s2.x + s2.y, 1e-12f));
        #pragma unroll
        for (int d = 0; d < 16; ++d) { float2 vv = base[d]; vv.x *= inv; vv.y *= inv; base[d] = vv; }
    }
    __syncthreads();

    // scores
    const float* mw = mask + (size_t)wloc * (NTOK * NTOK);
    for (int idx = t; idx < 4 * NTOK * NTOK; idx += 256) {
        int h = idx / 2401, rem = idx % 2401;
        int p = rem / 49, qq = rem % 49;
        const float2* qr = (const float2*)(q + p * QS + h * 32);
        const float2* kr = (const float2*)(kk + qq * KS + h * 32);
        float2 a0 = make_float2(0.f, 0.f), a1 = make_float2(0.f, 0.f);
        #pragma unroll
        for (int d = 0; d < 16; d += 2) {
            a0 = ffma2(qr[d], kr[d], a0);
            a1 = ffma2(qr[d + 1], kr[d + 1], a1);
        }
        float acc = a0.x + a0.y + a1.x + a1.y;
        int dy = p / WS - qq / WS + 6;
        int dx = p % WS - qq % WS + 6;
        at[idx] = fmaf(acc, g_scale[h], g_bias16[(dy * 13 + dx) * 4 + h] + mw[rem]);
    }
    __syncthreads();

    // softmax rows
    for (int idx = t; idx < 4 * NTOK; idx += 256) {
        float* row = at + idx * NTOK;
        float m = -1e30f;
        #pragma unroll 7
        for (int qq = 0; qq < NTOK; ++qq) m = fmaxf(m, row[qq]);
        float s = 0.f;
        #pragma unroll 7
        for (int qq = 0; qq < NTOK; ++qq) { float e = expf(row[qq] - m); row[qq] = e; s += e; }
        float inv = 1.f / s;
        #pragma unroll 7
        for (int qq = 0; qq < NTOK; ++qq) row[qq] *= inv;
    }
    __syncthreads();

    // o = attn @ v, write directly to g_o (window order, coalesced)
    const float2* v2 = (const float2*)v;
    for (int idx = t; idx < NTOK * 64; idx += 256) {
        int p = idx >> 6, cp = idx & 63, h = cp >> 4;
        const float* ar = at + (h * 49 + p) * 49;
        float2 acc = make_float2(0.f, 0.f);
        #pragma unroll 7
        for (int qq = 0; qq < NTOK; ++qq) {
            float a = ar[qq];
            acc = ffma2(make_float2(a, a), v2[qq * 64 + cp], acc);
        }
        *(float2*)(g_o + ((size_t)win * NTOK + p) * 128 + cp * 2) = acc;
    }
}

// ---------------- LN + residual: out[r] = base[r] + LN(y[r]) ----------------
__global__ void __launch_bounds__(256) k_ln_add(
    const float* __restrict__ base, const float* __restrict__ y,
    const float* __restrict__ g, const float* __restrict__ bta,
    float* __restrict__ out) {
    int t = threadIdx.x, lane = t & 31, warp = t >> 5;
    size_t r = (size_t)blockIdx.x * 8 + warp;
    const float4* yr = (const float4*)(y + r * 128);
    float4 vv = yr[lane];
    float s = vv.x + vv.y + vv.z + vv.w;
    #pragma unroll
    for (int o = 16; o; o >>= 1) s += __shfl_xor_sync(0xffffffffu, s, o);
    float m = s * (1.f / 128.f);
    float dx0 = vv.x - m, dx1 = vv.y - m, dx2 = vv.z - m, dx3 = vv.w - m;
    float vs = dx0 * dx0 + dx1 * dx1 + dx2 * dx2 + dx3 * dx3;
    #pragma unroll
    for (int o = 16; o; o >>= 1) vs += __shfl_xor_sync(0xffffffffu, vs, o);
    float inv = rsqrtf(vs * (1.f / 128.f) + 1e-3f);
    float4 bb = ((const float4*)(base + r * 128))[lane];
    float4 gg = ((const float4*)g)[lane];
    float4 be = ((const float4*)bta)[lane];
    float4 o4;
    o4.x = bb.x + dx0 * inv * gg.x + be.x;
    o4.y = bb.y + dx1 * inv * gg.y + be.y;
    o4.z = bb.z + dx2 * inv * gg.z + be.z;
    o4.w = bb.w + dx3 * inv * gg.w + be.w;
    ((float4*)(out + r * 128))[lane] = o4;
}

// ---------------- launch ----------------
extern "C" void kernel_launch(void* const* d_in, const int* in_sizes, int n_in,
                              void* d_out, int out_size) {
    const float* x           = (const float*)d_in[0];
    const float* mask        = (const float*)d_in[1];
    const float* norm1_g     = (const float*)d_in[2];
    const float* norm1_b     = (const float*)d_in[3];
    const float* qkv_w       = (const float*)d_in[4];
    const float* q_bias      = (const float*)d_in[5];
    const float* v_bias      = (const float*)d_in[6];
    const float* logit_scale = (const float*)d_in[7];
    const float* rpe_w1      = (const float*)d_in[8];
    const float* rpe_b1      = (const float*)d_in[9];
    const float* rpe_w2      = (const float*)d_in[10];
    const float* proj_w      = (const float*)d_in[11];
    const float* proj_b      = (const float*)d_in[12];
    const float* norm2_g     = (const float*)d_in[13];
    const float* norm2_b     = (const float*)d_in[14];
    const float* fc1_w       = (const float*)d_in[15];
    const float* fc1_b       = (const float*)d_in[16];
    const float* fc2_w       = (const float*)d_in[17];
    const float* fc2_b       = (const float*)d_in[18];
    float* out = (float*)d_out;

    float *p_qkv, *p_o, *p_attn, *p_x1, *p_h, *p_qb;
    cudaGetSymbolAddress((void**)&p_qkv,  g_qkv);
    cudaGetSymbolAddress((void**)&p_o,    g_o);
    cudaGetSymbolAddress((void**)&p_attn, g_attn_out);
    cudaGetSymbolAddress((void**)&p_x1,   g_x1);
    cudaGetSymbolAddress((void**)&p_h,    g_h);
    cudaGetSymbolAddress((void**)&p_qb,   g_qkvbias);

    size_t smem_core = SMEM_CORE_FLOATS * sizeof(float);
    cudaFuncSetAttribute(k_core, cudaFuncAttributeMaxDynamicSharedMemorySize, (int)smem_core);

    k_prep<<<170, 128>>>(logit_scale, rpe_w1, rpe_b1, rpe_w2, q_bias, v_bias);

    dim3 g_qkv_grid(NPIX / 64, 3);
    k_gemm<128, 384, 0><<<g_qkv_grid, 256>>>(x, qkv_w, p_qb, p_qkv);

    k_core<<<NWIN_TOT, 256, smem_core>>>(mask);

    dim3 g_proj_grid(NPIX / 64, 1);
    k_gemm<128, 128, 1><<<g_proj_grid, 256>>>(p_o, proj_w, proj_b, p_attn);

    k_ln_add<<<NPIX / 8, 256>>>(x, p_attn, norm1_g, norm1_b, p_x1);

    dim3 g_fc1_grid(NPIX / 64, 4);
    k_gemm<128, 512, 2><<<g_fc1_grid, 256>>>(p_x1, fc1_w, fc1_b, p_h);

    dim3 g_fc2_grid(NPIX / 64, 1);
    k_gemm<512, 128, 3><<<g_fc2_grid, 256>>>(p_h, fc2_w, fc2_b, p_o);

    k_ln_add<<<NPIX / 8, 256>>>(p_x1, p_o, norm2_g, norm2_b, out);
}